// round 1
// baseline (speedup 1.0000x reference)
#include <cuda_runtime.h>
#include <math.h>

#define TPB 256
#define ROWS_PER_BLK 64
#define DIN 64
#define HID 128
#define NBINS 256
#define MAXBLK 8192

#define SX_STRIDE 68
#define SH_STRIDE 132

// smem layout (floats)
#define OFF_W1 0                                   // 64*128   = 8192
#define OFF_W2 (OFF_W1 + DIN*HID)                  // 128*256  = 32768
#define OFF_X  (OFF_W2 + HID*NBINS)                // 64*68    = 4352
#define OFF_H  (OFF_X + ROWS_PER_BLK*SX_STRIDE)    // 64*132   = 8448
#define OFF_SC (OFF_H + ROWS_PER_BLK*SH_STRIDE)    // 64 scores
#define OFF_YB (OFF_SC + ROWS_PER_BLK)             // 64 ybins (int slots)
#define SMEM_FLOATS (OFF_YB + ROWS_PER_BLK)        // 53888 floats = 215552 B

typedef unsigned long long ull;

__device__ double g_partials[MAXBLK];

__device__ __forceinline__ ull pack2(float lo, float hi) {
    ull r;
    asm("mov.b64 %0, {%1, %2};" : "=l"(r) : "f"(lo), "f"(hi));
    return r;
}
__device__ __forceinline__ float2 unpack2(ull v) {
    float2 f;
    asm("mov.b64 {%0, %1}, %2;" : "=f"(f.x), "=f"(f.y) : "l"(v));
    return f;
}
__device__ __forceinline__ ull fma2(ull a, ull b, ull c) {
    ull d;
    asm("fma.rn.f32x2 %0, %1, %2, %3;" : "=l"(d) : "l"(a), "l"(b), "l"(c));
    return d;
}

// exact-GELU matching jax.nn.gelu(approximate=False)
__device__ __forceinline__ float gelu_exact(float z) {
    return 0.5f * z * (1.0f + erff(z * 0.70710678118654752440f));
}

// exp matching XLA's "poly(t) then +1" rounding structure for tiny |t|
__device__ __forceinline__ float exp_match(float t) {
    if (fabsf(t) < 6.103515625e-05f) {           // 2^-14
        float s = fmaf(0.5f * t, t, t);           // RN(t + t^2/2)
        return 1.0f + s;                          // RN(1 + s)
    }
    return expf(t);
}

__global__ void __launch_bounds__(TPB, 1)
mlp_loss_kernel(const float* __restrict__ X, const float* __restrict__ Y,
                const float* __restrict__ W1, const float* __restrict__ B1,
                const float* __restrict__ W2, const float* __restrict__ B2)
{
    extern __shared__ float sm[];
    const int tid = threadIdx.x;
    const int row0 = blockIdx.x * ROWS_PER_BLK;

    // ---- load weights + x tile into smem ----
    for (int i = tid; i < DIN * HID / 4; i += TPB)
        ((float4*)(sm + OFF_W1))[i] = ((const float4*)W1)[i];
    for (int i = tid; i < HID * NBINS / 4; i += TPB)
        ((float4*)(sm + OFF_W2))[i] = ((const float4*)W2)[i];
    {
        const float4* xg = (const float4*)(X + (size_t)row0 * DIN);
        for (int i = tid; i < ROWS_PER_BLK * (DIN / 4); i += TPB) {
            int r = i / (DIN / 4), q = i % (DIN / 4);
            *((float4*)(sm + OFF_X + r * SX_STRIDE + q * 4)) = xg[i];
        }
    }
    // ---- y-bin per row: emulates searchsorted(borders, y, 'left')-1, clipped ----
    if (tid < ROWS_PER_BLK) {
        float yv = Y[row0 + tid];
        float t = yv * 256.0f;                      // exact (x 2^8)
        int b = (int)ceilf(t) - 1;                  // exact-border -> lower bin
        b = min(max(b, 0), NBINS - 1);
        ((int*)(sm + OFF_YB))[tid] = b;
    }
    __syncthreads();

    const int rg = tid >> 4;    // row group (16 groups x 4 rows)
    const int cg = tid & 15;    // col group

    // ================= GEMM1: z = x @ W1, h = gelu(z + b1) =================
    {
        ull a1[4][2][2];
        #pragma unroll
        for (int i = 0; i < 4; i++)
            #pragma unroll
            for (int g = 0; g < 2; g++) { a1[i][g][0] = 0ull; a1[i][g][1] = 0ull; }

        const float* sX = sm + OFF_X + rg * 4 * SX_STRIDE;
        const float* sW1 = sm + OFF_W1;
        #pragma unroll 4
        for (int k = 0; k < DIN; k++) {
            ull xd[4];
            #pragma unroll
            for (int i = 0; i < 4; i++) {
                float xv = sX[i * SX_STRIDE + k];
                xd[i] = pack2(xv, xv);
            }
            #pragma unroll
            for (int g = 0; g < 2; g++) {
                ulonglong2 w = *(const ulonglong2*)(sW1 + k * HID + 4 * cg + 64 * g);
                #pragma unroll
                for (int i = 0; i < 4; i++) {
                    a1[i][g][0] = fma2(xd[i], w.x, a1[i][g][0]);
                    a1[i][g][1] = fma2(xd[i], w.y, a1[i][g][1]);
                }
            }
        }
        #pragma unroll
        for (int g = 0; g < 2; g++) {
            float4 bb = *(const float4*)(B1 + 4 * cg + 64 * g);
            #pragma unroll
            for (int i = 0; i < 4; i++) {
                float2 p0 = unpack2(a1[i][g][0]);
                float2 p1 = unpack2(a1[i][g][1]);
                float4 hv;
                hv.x = gelu_exact(p0.x + bb.x);
                hv.y = gelu_exact(p0.y + bb.y);
                hv.z = gelu_exact(p1.x + bb.z);
                hv.w = gelu_exact(p1.y + bb.w);
                *(float4*)(sm + OFF_H + (rg * 4 + i) * SH_STRIDE + 4 * cg + 64 * g) = hv;
            }
        }
    }
    __syncthreads();

    // ================= GEMM2: logits = h @ W2 + b2 =================
    ull a2[4][4][2];
    #pragma unroll
    for (int i = 0; i < 4; i++)
        #pragma unroll
        for (int g = 0; g < 4; g++) { a2[i][g][0] = 0ull; a2[i][g][1] = 0ull; }

    {
        const float* sH = sm + OFF_H + rg * 4 * SH_STRIDE;
        const float* sW2 = sm + OFF_W2;
        #pragma unroll 2
        for (int k = 0; k < HID; k++) {
            ull hd[4];
            #pragma unroll
            for (int i = 0; i < 4; i++) {
                float hv = sH[i * SH_STRIDE + k];
                hd[i] = pack2(hv, hv);
            }
            #pragma unroll
            for (int g = 0; g < 4; g++) {
                ulonglong2 w = *(const ulonglong2*)(sW2 + k * NBINS + 4 * cg + 64 * g);
                #pragma unroll
                for (int i = 0; i < 4; i++) {
                    a2[i][g][0] = fma2(hd[i], w.x, a2[i][g][0]);
                    a2[i][g][1] = fma2(hd[i], w.y, a2[i][g][1]);
                }
            }
        }
    }

    // ---- epilogue: per-row softmax density at y-bin, -log, exact fp32 semantics ----
    float l[4][16];
    #pragma unroll
    for (int g = 0; g < 4; g++) {
        float4 bb = *(const float4*)(B2 + 4 * cg + 64 * g);
        #pragma unroll
        for (int i = 0; i < 4; i++) {
            float2 p0 = unpack2(a2[i][g][0]);
            float2 p1 = unpack2(a2[i][g][1]);
            l[i][g * 4 + 0] = p0.x + bb.x;
            l[i][g * 4 + 1] = p0.y + bb.y;
            l[i][g * 4 + 2] = p1.x + bb.z;
            l[i][g * 4 + 3] = p1.y + bb.w;
        }
    }

    const int* sYB = (const int*)(sm + OFF_YB);
    #pragma unroll
    for (int i = 0; i < 4; i++) {
        int r = rg * 4 + i;
        int yb = sYB[r];
        float mx = -INFINITY, lyv = -INFINITY;
        #pragma unroll
        for (int g = 0; g < 4; g++) {
            #pragma unroll
            for (int jj = 0; jj < 4; jj++) {
                float v = l[i][g * 4 + jj];
                mx = fmaxf(mx, v);
                int col = 4 * cg + 64 * g + jj;
                if (col == yb) lyv = v;
            }
        }
        #pragma unroll
        for (int o = 1; o < 16; o <<= 1) {
            mx = fmaxf(mx, __shfl_xor_sync(0xffffffffu, mx, o));
        }
        #pragma unroll
        for (int o = 1; o < 16; o <<= 1) {
            lyv = fmaxf(lyv, __shfl_xor_sync(0xffffffffu, lyv, o));
        }
        float s = 0.0f;
        #pragma unroll
        for (int j = 0; j < 16; j++) s += exp_match(l[i][j] - mx);
        #pragma unroll
        for (int o = 1; o < 16; o <<= 1) {
            s += __shfl_xor_sync(0xffffffffu, s, o);
        }
        if (cg == 0) {
            float e = exp_match(lyv - mx);
            float mass = e / s;                       // s == 256.0 -> exact
            float dens = mass * 256.0f;               // / width, width = 2^-8 exact
            float d2 = dens + 1.401298464324817e-45f; // + fl32(1e-45)
            float u = d2 - 1.0f;
            float sc;
            if (fabsf(u) < 1.220703125e-04f)          // 2^-13
                sc = fmaf(0.5f * u, u, -u);           // RN(u^2/2 - u) = -RN(log1p(u))
            else
                sc = -logf(d2);
            sm[OFF_SC + r] = sc;
        }
    }
    __syncthreads();

    if (tid == 0) {
        double bs = 0.0;
        const float* sc = sm + OFF_SC;
        for (int r = 0; r < ROWS_PER_BLK; r++) bs += (double)sc[r];
        g_partials[blockIdx.x] = bs;
    }
}

__global__ void reduce_kernel(float* out, int nb) {
    __shared__ double sd[256];
    int tid = threadIdx.x;
    double a = 0.0;
    for (int i = tid; i < nb; i += 256) a += g_partials[i];
    sd[tid] = a;
    __syncthreads();
    for (int s = 128; s > 0; s >>= 1) {
        if (tid < s) sd[tid] += sd[tid + s];
        __syncthreads();
    }
    if (tid == 0) out[0] = (float)sd[0];
}

extern "C" void kernel_launch(void* const* d_in, const int* in_sizes, int n_in,
                              void* d_out, int out_size)
{
    // dispatch by element count (robust to ordering): X=N*64, Y=N, W1=8192, b1=128, W2=32768, b2=256
    const float *X = 0, *Y = 0, *W1 = 0, *B1 = 0, *W2 = 0, *B2 = 0;
    long long nmax = 0;
    for (int i = 0; i < n_in; i++)
        if ((long long)in_sizes[i] > nmax) nmax = in_sizes[i];
    for (int i = 0; i < n_in; i++) {
        long long s = in_sizes[i];
        const float* p = (const float*)d_in[i];
        if (s == nmax)                X = p;       // N*64
        else if (s == nmax / DIN)     Y = p;       // N
        else if (s == DIN * HID)      W1 = p;      // 8192
        else if (s == HID)            B1 = p;      // 128
        else if (s == HID * NBINS)    W2 = p;      // 32768
        else if (s == NBINS)          B2 = p;      // 256
    }
    int nrows = (int)(nmax / DIN);
    int nb = nrows / ROWS_PER_BLK;

    size_t smem = SMEM_FLOATS * sizeof(float);
    cudaFuncSetAttribute(mlp_loss_kernel,
                         cudaFuncAttributeMaxDynamicSharedMemorySize, (int)smem);
    mlp_loss_kernel<<<nb, TPB, smem>>>(X, Y, W1, B1, W2, B2);
    reduce_kernel<<<1, 256>>>((float*)d_out, nb);
}

// round 2
// speedup vs baseline: 1.1402x; 1.1402x over previous
#include <cuda_runtime.h>
#include <math.h>

#define TPB 512
#define ROWS_PER_BLK 64
#define DIN 64
#define HID 128
#define NBINS 256
#define MAXGRID 1024

#define SX_STRIDE 68
#define SH_STRIDE 132

// smem layout (floats)
#define OFF_W1 0                                    // 64*128   = 8192
#define OFF_W2 (OFF_W1 + DIN*HID)                   // 128*256  = 32768
#define OFF_X  (OFF_W2 + HID*NBINS)                 // 64*68    = 4352
#define OFF_H  (OFF_X + ROWS_PER_BLK*SX_STRIDE)     // 64*132   = 8448
#define OFF_SC (OFF_H + ROWS_PER_BLK*SH_STRIDE)     // 32 doubles = 64 float slots
#define OFF_YB0 (OFF_SC + 64)                       // 64 ints
#define OFF_YB1 (OFF_YB0 + 64)                      // 64 ints
#define SMEM_FLOATS (OFF_YB1 + 64)

typedef unsigned long long ull;

__device__ double g_partials[MAXGRID];
__device__ unsigned int g_done = 0;

__device__ __forceinline__ ull pack2(float lo, float hi) {
    ull r;
    asm("mov.b64 %0, {%1, %2};" : "=l"(r) : "f"(lo), "f"(hi));
    return r;
}
__device__ __forceinline__ float2 unpack2(ull v) {
    float2 f;
    asm("mov.b64 {%0, %1}, %2;" : "=f"(f.x), "=f"(f.y) : "l"(v));
    return f;
}
__device__ __forceinline__ ull fma2(ull a, ull b, ull c) {
    ull d;
    asm("fma.rn.f32x2 %0, %1, %2, %3;" : "=l"(d) : "l"(a), "l"(b), "l"(c));
    return d;
}

// exact-GELU matching jax.nn.gelu(approximate=False)
__device__ __forceinline__ float gelu_exact(float z) {
    return 0.5f * z * (1.0f + erff(z * 0.70710678118654752440f));
}

// exp matching XLA's "poly(t) then +1" rounding structure for tiny |t|
__device__ __forceinline__ float exp_match(float t) {
    if (fabsf(t) < 6.103515625e-05f) {            // 2^-14
        float s = fmaf(0.5f * t, t, t);            // RN(t + t^2/2)
        return 1.0f + s;                           // RN(1 + s)
    }
    return expf(t);
}

__global__ void __launch_bounds__(TPB, 1)
mlp_loss_kernel(const float* __restrict__ X, const float* __restrict__ Y,
                const float* __restrict__ W1, const float* __restrict__ B1,
                const float* __restrict__ W2, const float* __restrict__ B2,
                float* __restrict__ out, int NT)
{
    extern __shared__ float sm[];
    const int tid = threadIdx.x;
    const int bid = blockIdx.x;
    const int stride = gridDim.x;

    // ---- prologue: weights into smem ONCE ----
    for (int i = tid; i < DIN * HID / 4; i += TPB)
        ((float4*)(sm + OFF_W1))[i] = ((const float4*)W1)[i];
    for (int i = tid; i < HID * NBINS / 4; i += TPB)
        ((float4*)(sm + OFF_W2))[i] = ((const float4*)W2)[i];

    // ---- preload first tile (t = bid) ----
    {
        int t0 = bid;
        const float4* xg = (const float4*)(X + (size_t)t0 * ROWS_PER_BLK * DIN);
        #pragma unroll
        for (int j = 0; j < 2; j++) {
            int idx = tid + j * TPB;             // 0..1023
            float4 v = xg[idx];
            int r = idx >> 4, q = idx & 15;
            *((float4*)(sm + OFF_X + r * SX_STRIDE + q * 4)) = v;
        }
        if (tid < ROWS_PER_BLK) {
            float yv = Y[(size_t)t0 * ROWS_PER_BLK + tid];
            float tt = yv * 256.0f;
            int b = (int)ceilf(tt) - 1;
            b = min(max(b, 0), NBINS - 1);
            ((int*)(sm + OFF_YB0))[tid] = b;
        }
    }
    __syncthreads();

    const int rg = tid >> 4;    // 32 row groups x 2 rows
    const int cg = tid & 15;    // 16 col groups

    double acc = 0.0;
    int buf = 0;

    for (int t = bid; t < NT; t += stride) {
        const int tn = t + stride;
        const bool hn = tn < NT;

        // ---- prefetch next tile into registers ----
        float4 p0, p1; float py = 0.0f;
        if (hn) {
            const float4* xg = (const float4*)(X + (size_t)tn * ROWS_PER_BLK * DIN);
            p0 = xg[tid];
            p1 = xg[tid + TPB];
            if (tid < ROWS_PER_BLK) py = Y[(size_t)tn * ROWS_PER_BLK + tid];
        }

        // ================= GEMM1: h = gelu(x @ W1 + b1) =================
        {
            ull a1[2][2][2];
            #pragma unroll
            for (int i = 0; i < 2; i++)
                #pragma unroll
                for (int g = 0; g < 2; g++) { a1[i][g][0] = 0ull; a1[i][g][1] = 0ull; }

            const float* sX = sm + OFF_X + (rg * 2) * SX_STRIDE;
            const float* sW1 = sm + OFF_W1;
            #pragma unroll 4
            for (int k = 0; k < DIN; k++) {
                ull xd[2];
                #pragma unroll
                for (int i = 0; i < 2; i++) {
                    float xv = sX[i * SX_STRIDE + k];
                    xd[i] = pack2(xv, xv);
                }
                #pragma unroll
                for (int g = 0; g < 2; g++) {
                    ulonglong2 w = *(const ulonglong2*)(sW1 + k * HID + 4 * cg + 64 * g);
                    #pragma unroll
                    for (int i = 0; i < 2; i++) {
                        a1[i][g][0] = fma2(xd[i], w.x, a1[i][g][0]);
                        a1[i][g][1] = fma2(xd[i], w.y, a1[i][g][1]);
                    }
                }
            }
            #pragma unroll
            for (int g = 0; g < 2; g++) {
                float4 bb = *(const float4*)(B1 + 4 * cg + 64 * g);
                #pragma unroll
                for (int i = 0; i < 2; i++) {
                    float2 q0 = unpack2(a1[i][g][0]);
                    float2 q1 = unpack2(a1[i][g][1]);
                    float4 hv;
                    hv.x = gelu_exact(q0.x + bb.x);
                    hv.y = gelu_exact(q0.y + bb.y);
                    hv.z = gelu_exact(q1.x + bb.z);
                    hv.w = gelu_exact(q1.y + bb.w);
                    *(float4*)(sm + OFF_H + (rg * 2 + i) * SH_STRIDE + 4 * cg + 64 * g) = hv;
                }
            }
        }
        __syncthreads();   // H ready; X consumed

        // ---- store prefetched tile (X now free; YB into other buffer) ----
        if (hn) {
            int idx0 = tid;
            *((float4*)(sm + OFF_X + (idx0 >> 4) * SX_STRIDE + (idx0 & 15) * 4)) = p0;
            int idx1 = tid + TPB;
            *((float4*)(sm + OFF_X + (idx1 >> 4) * SX_STRIDE + (idx1 & 15) * 4)) = p1;
            if (tid < ROWS_PER_BLK) {
                float tt = py * 256.0f;
                int b = (int)ceilf(tt) - 1;
                b = min(max(b, 0), NBINS - 1);
                ((int*)(sm + (buf ? OFF_YB0 : OFF_YB1)))[tid] = b;
            }
        }

        // ================= GEMM2: logits = h @ W2 + b2 =================
        ull a2[2][4][2];
        #pragma unroll
        for (int i = 0; i < 2; i++)
            #pragma unroll
            for (int g = 0; g < 4; g++) { a2[i][g][0] = 0ull; a2[i][g][1] = 0ull; }

        {
            const float* sH = sm + OFF_H + (rg * 2) * SH_STRIDE;
            const float* sW2 = sm + OFF_W2;
            #pragma unroll 2
            for (int k = 0; k < HID; k++) {
                ull hd[2];
                #pragma unroll
                for (int i = 0; i < 2; i++) {
                    float hv = sH[i * SH_STRIDE + k];
                    hd[i] = pack2(hv, hv);
                }
                #pragma unroll
                for (int g = 0; g < 4; g++) {
                    ulonglong2 w = *(const ulonglong2*)(sW2 + k * NBINS + 4 * cg + 64 * g);
                    #pragma unroll
                    for (int i = 0; i < 2; i++) {
                        a2[i][g][0] = fma2(hd[i], w.x, a2[i][g][0]);
                        a2[i][g][1] = fma2(hd[i], w.y, a2[i][g][1]);
                    }
                }
            }
        }

        // ---- epilogue: per-row softmax density at y-bin, -log ----
        float l[2][16];
        #pragma unroll
        for (int g = 0; g < 4; g++) {
            float4 bb = *(const float4*)(B2 + 4 * cg + 64 * g);
            #pragma unroll
            for (int i = 0; i < 2; i++) {
                float2 q0 = unpack2(a2[i][g][0]);
                float2 q1 = unpack2(a2[i][g][1]);
                l[i][g * 4 + 0] = q0.x + bb.x;
                l[i][g * 4 + 1] = q0.y + bb.y;
                l[i][g * 4 + 2] = q1.x + bb.z;
                l[i][g * 4 + 3] = q1.y + bb.w;
            }
        }

        const int* sYB = (const int*)(sm + (buf ? OFF_YB1 : OFF_YB0));
        #pragma unroll
        for (int i = 0; i < 2; i++) {
            int r = rg * 2 + i;
            int yb = sYB[r];
            float mx = -INFINITY, lyv = -INFINITY;
            #pragma unroll
            for (int g = 0; g < 4; g++) {
                #pragma unroll
                for (int jj = 0; jj < 4; jj++) {
                    float v = l[i][g * 4 + jj];
                    mx = fmaxf(mx, v);
                    int col = 4 * cg + 64 * g + jj;
                    if (col == yb) lyv = v;
                }
            }
            #pragma unroll
            for (int o = 1; o < 16; o <<= 1)
                mx = fmaxf(mx, __shfl_xor_sync(0xffffffffu, mx, o));
            #pragma unroll
            for (int o = 1; o < 16; o <<= 1)
                lyv = fmaxf(lyv, __shfl_xor_sync(0xffffffffu, lyv, o));
            float s = 0.0f;
            #pragma unroll
            for (int j = 0; j < 16; j++) s += exp_match(l[i][j] - mx);
            #pragma unroll
            for (int o = 1; o < 16; o <<= 1)
                s += __shfl_xor_sync(0xffffffffu, s, o);
            if (cg == 0) {
                float e = exp_match(lyv - mx);
                float mass = e / s;
                float dens = mass * 256.0f;
                float d2 = dens + 1.401298464324817e-45f;
                float u = d2 - 1.0f;
                float sc;
                if (fabsf(u) < 1.220703125e-04f)       // 2^-13
                    sc = fmaf(0.5f * u, u, -u);        // -RN(log1p(u))
                else
                    sc = -logf(d2);
                acc += (double)sc;
            }
        }
        __syncthreads();   // protect H rewrite + X/YB stores for next iter
        buf ^= 1;
    }

    // ---- deterministic block reduction ----
    if (cg == 0) ((double*)(sm + OFF_SC))[rg] = acc;
    __syncthreads();
    if (tid == 0) {
        double bs = 0.0;
        const double* sd = (const double*)(sm + OFF_SC);
        #pragma unroll
        for (int r = 0; r < 32; r++) bs += sd[r];
        g_partials[bid] = bs;
        __threadfence();
        unsigned int old = atomicInc(&g_done, gridDim.x - 1);
        if (old == gridDim.x - 1) {
            // last CTA: fixed-order sum -> deterministic output
            double tot = 0.0;
            for (int i = 0; i < (int)gridDim.x; i++)
                tot += ((volatile double*)g_partials)[i];
            out[0] = (float)tot;
        }
    }
}

extern "C" void kernel_launch(void* const* d_in, const int* in_sizes, int n_in,
                              void* d_out, int out_size)
{
    const float *X = 0, *Y = 0, *W1 = 0, *B1 = 0, *W2 = 0, *B2 = 0;
    long long nmax = 0;
    for (int i = 0; i < n_in; i++)
        if ((long long)in_sizes[i] > nmax) nmax = in_sizes[i];
    for (int i = 0; i < n_in; i++) {
        long long s = in_sizes[i];
        const float* p = (const float*)d_in[i];
        if (s == nmax)                X = p;       // N*64
        else if (s == nmax / DIN)     Y = p;       // N
        else if (s == DIN * HID)      W1 = p;      // 8192
        else if (s == HID)            B1 = p;      // 128
        else if (s == HID * NBINS)    W2 = p;      // 32768
        else if (s == NBINS)          B2 = p;      // 256
    }
    int nrows = (int)(nmax / DIN);
    int NT = nrows / ROWS_PER_BLK;

    int nsm = 148;
    cudaDeviceGetAttribute(&nsm, cudaDevAttrMultiProcessorCount, 0);
    if (nsm > MAXGRID) nsm = MAXGRID;
    int grid = (NT < nsm) ? NT : nsm;

    size_t smem = SMEM_FLOATS * sizeof(float);
    cudaFuncSetAttribute(mlp_loss_kernel,
                         cudaFuncAttributeMaxDynamicSharedMemorySize, (int)smem);
    mlp_loss_kernel<<<grid, TPB, smem>>>(X, Y, W1, B1, W2, B2, (float*)d_out, NT);
}

// round 3
// speedup vs baseline: 1.6666x; 1.4618x over previous
#include <cuda_runtime.h>
#include <math.h>

#define TPB 512
#define RPB 64
#define DIN 64
#define HID 128
#define NBINS 256
#define MAXGRID 1024
#define SXS 68
#define SHS 132

// smem float offsets
#define OFF_W1 0
#define OFF_W2 (OFF_W1 + DIN*HID)          // 8192
#define OFF_X  (OFF_W2 + HID*NBINS)        // 40960
#define OFF_H  (OFF_X + RPB*SXS)           // 45312
#define OFF_EPMX (OFF_H + RPB*SHS)         // 53760
#define OFF_EPLY (OFF_EPMX + RPB*8)        // 54272
#define OFF_EPS  (OFF_EPLY + RPB*8)        // 54784
#define OFF_YB0  (OFF_EPS + RPB*8)         // 55296
#define OFF_YB1  (OFF_YB0 + RPB)           // 55360
#define OFF_DACC (OFF_YB1 + RPB)           // 55424 : 64 doubles (128 float slots)
#define SMEM_FLOATS (OFF_DACC + 128)       // 55552 floats = 222208 B

typedef unsigned long long ull;

__device__ double g_partials[MAXGRID];
__device__ unsigned int g_done = 0;

__device__ __forceinline__ ull pack2(float lo, float hi) {
    ull r;
    asm("mov.b64 %0, {%1, %2};" : "=l"(r) : "f"(lo), "f"(hi));
    return r;
}
__device__ __forceinline__ float2 unpack2(ull v) {
    float2 f;
    asm("mov.b64 {%0, %1}, %2;" : "=f"(f.x), "=f"(f.y) : "l"(v));
    return f;
}
__device__ __forceinline__ ull fma2(ull a, ull b, ull c) {
    ull d;
    asm("fma.rn.f32x2 %0, %1, %2, %3;" : "=l"(d) : "l"(a), "l"(b), "l"(c));
    return d;
}

// exact-GELU matching jax.nn.gelu(approximate=False)
__device__ __forceinline__ float gelu_exact(float z) {
    return 0.5f * z * (1.0f + erff(z * 0.70710678118654752440f));
}

// exp matching XLA's rounding structure for tiny |t|
__device__ __forceinline__ float exp_match(float t) {
    if (fabsf(t) < 6.103515625e-05f) {            // 2^-14
        float s = fmaf(0.5f * t, t, t);            // RN(t + t^2/2)
        return 1.0f + s;                           // RN(1 + s)
    }
    return expf(t);
}

__global__ void __launch_bounds__(TPB, 1)
mlp_loss_kernel(const float* __restrict__ X, const float* __restrict__ Y,
                const float* __restrict__ W1, const float* __restrict__ B1,
                const float* __restrict__ W2, const float* __restrict__ B2,
                float* __restrict__ out, int NT)
{
    extern __shared__ float sm[];
    const int tid = threadIdx.x;
    const int bid = blockIdx.x;
    const int stride = gridDim.x;

    const int wrp  = tid >> 5;
    const int lane = tid & 31;
    const int band = wrp >> 3;       // 0..1   (32-row band)
    const int cw   = wrp & 7;        // 0..7   (col warp)
    const int rsub = lane >> 2;      // 0..7
    const int csub = lane & 3;       // 0..3
    // thread rows: band*32 + i*8 + rsub, i=0..3
    const int rbase = band * 32 + rsub;

    // ---- weights into smem ONCE ----
    for (int i = tid; i < DIN * HID / 4; i += TPB)
        ((float4*)(sm + OFF_W1))[i] = ((const float4*)W1)[i];
    for (int i = tid; i < HID * NBINS / 4; i += TPB)
        ((float4*)(sm + OFF_W2))[i] = ((const float4*)W2)[i];

    // ---- persistent bias fragments ----
    const int c1base = cw * 16 + csub * 4;       // GEMM1 cols
    const int c2base = cw * 32 + csub * 8;       // GEMM2 cols
    float4 b1f = *(const float4*)(B1 + c1base);
    float4 b2f0 = *(const float4*)(B2 + c2base);
    float4 b2f1 = *(const float4*)(B2 + c2base + 4);

    // ---- preload first tile ----
    {
        const float4* xg = (const float4*)(X + (size_t)bid * RPB * DIN);
        #pragma unroll
        for (int j = 0; j < 2; j++) {
            int idx = tid + j * TPB;
            float4 v = xg[idx];
            *((float4*)(sm + OFF_X + (idx >> 4) * SXS + (idx & 15) * 4)) = v;
        }
        if (tid < RPB) {
            float yv = Y[(size_t)bid * RPB + tid];
            float tt = yv * 256.0f;
            int b = (int)ceilf(tt) - 1;
            b = min(max(b, 0), NBINS - 1);
            ((int*)(sm + OFF_YB0))[tid] = b;
        }
    }
    __syncthreads();

    double acc = 0.0;
    int buf = 0;

    for (int t = bid; t < NT; t += stride) {
        const int tn = t + stride;
        const bool hn = tn < NT;

        // ---- prefetch next tile into registers ----
        float4 p0, p1; float py = 0.0f;
        if (hn) {
            const float4* xg = (const float4*)(X + (size_t)tn * RPB * DIN);
            p0 = xg[tid];
            p1 = xg[tid + TPB];
            if (tid < RPB) py = Y[(size_t)tn * RPB + tid];
        }

        // ================= GEMM1: h = gelu(x @ W1 + b1) =================
        {
            ull a1[4][2];
            #pragma unroll
            for (int i = 0; i < 4; i++) { a1[i][0] = 0ull; a1[i][1] = 0ull; }

            const float* sX = sm + OFF_X + rbase * SXS;
            const float* sW1 = sm + OFF_W1 + c1base;
            #pragma unroll 4
            for (int k4 = 0; k4 < DIN / 4; k4++) {
                float xf[4][4];
                #pragma unroll
                for (int i = 0; i < 4; i++) {
                    float4 v = *(const float4*)(sX + i * 8 * SXS + 4 * k4);
                    xf[i][0] = v.x; xf[i][1] = v.y; xf[i][2] = v.z; xf[i][3] = v.w;
                }
                #pragma unroll
                for (int kk = 0; kk < 4; kk++) {
                    ulonglong2 wv = *(const ulonglong2*)(sW1 + (4 * k4 + kk) * HID);
                    #pragma unroll
                    for (int i = 0; i < 4; i++) {
                        ull xd = pack2(xf[i][kk], xf[i][kk]);
                        a1[i][0] = fma2(xd, wv.x, a1[i][0]);
                        a1[i][1] = fma2(xd, wv.y, a1[i][1]);
                    }
                }
            }
            // bias + gelu + store h
            #pragma unroll
            for (int i = 0; i < 4; i++) {
                float2 q0 = unpack2(a1[i][0]);
                float2 q1 = unpack2(a1[i][1]);
                float4 hv;
                hv.x = gelu_exact(q0.x + b1f.x);
                hv.y = gelu_exact(q0.y + b1f.y);
                hv.z = gelu_exact(q1.x + b1f.z);
                hv.w = gelu_exact(q1.y + b1f.w);
                *(float4*)(sm + OFF_H + (rbase + i * 8) * SHS + c1base) = hv;
            }
        }
        __syncthreads();   // S1: X reads done, H writes visible

        // ---- store prefetched X tile + y-bins ----
        if (hn) {
            *((float4*)(sm + OFF_X + (tid >> 4) * SXS + (tid & 15) * 4)) = p0;
            int idx1 = tid + TPB;
            *((float4*)(sm + OFF_X + (idx1 >> 4) * SXS + (idx1 & 15) * 4)) = p1;
            if (tid < RPB) {
                float tt = py * 256.0f;
                int b = (int)ceilf(tt) - 1;
                b = min(max(b, 0), NBINS - 1);
                ((int*)(sm + (buf ? OFF_YB0 : OFF_YB1)))[tid] = b;
            }
        }

        // ================= GEMM2: logits = h @ W2 + b2 =================
        ull a2[4][4];
        #pragma unroll
        for (int i = 0; i < 4; i++)
            #pragma unroll
            for (int g = 0; g < 4; g++) a2[i][g] = 0ull;

        {
            const float* sH = sm + OFF_H + rbase * SHS;
            const float* sW2 = sm + OFF_W2 + c2base;
            #pragma unroll 4
            for (int k4 = 0; k4 < HID / 4; k4++) {
                float hf[4][4];
                #pragma unroll
                for (int i = 0; i < 4; i++) {
                    float4 v = *(const float4*)(sH + i * 8 * SHS + 4 * k4);
                    hf[i][0] = v.x; hf[i][1] = v.y; hf[i][2] = v.z; hf[i][3] = v.w;
                }
                #pragma unroll
                for (int kk = 0; kk < 4; kk++) {
                    const float* wp = sW2 + (4 * k4 + kk) * NBINS;
                    ulonglong2 wa = *(const ulonglong2*)(wp);
                    ulonglong2 wb = *(const ulonglong2*)(wp + 4);
                    #pragma unroll
                    for (int i = 0; i < 4; i++) {
                        ull hd = pack2(hf[i][kk], hf[i][kk]);
                        a2[i][0] = fma2(hd, wa.x, a2[i][0]);
                        a2[i][1] = fma2(hd, wa.y, a2[i][1]);
                        a2[i][2] = fma2(hd, wb.x, a2[i][2]);
                        a2[i][3] = fma2(hd, wb.y, a2[i][3]);
                    }
                }
            }
        }

        // ---- epilogue phase 1: logits, per-warp-band max / ly ----
        float l[4][8];
        #pragma unroll
        for (int i = 0; i < 4; i++) {
            float2 q0 = unpack2(a2[i][0]);
            float2 q1 = unpack2(a2[i][1]);
            float2 q2 = unpack2(a2[i][2]);
            float2 q3 = unpack2(a2[i][3]);
            l[i][0] = q0.x + b2f0.x; l[i][1] = q0.y + b2f0.y;
            l[i][2] = q1.x + b2f0.z; l[i][3] = q1.y + b2f0.w;
            l[i][4] = q2.x + b2f1.x; l[i][5] = q2.y + b2f1.y;
            l[i][6] = q3.x + b2f1.z; l[i][7] = q3.y + b2f1.w;
        }

        const int* sYB = (const int*)(sm + (buf ? OFF_YB1 : OFF_YB0));
        int ybr[4];
        #pragma unroll
        for (int i = 0; i < 4; i++) {
            int r = rbase + i * 8;
            ybr[i] = sYB[r];
            float mx = l[i][0], ly = -INFINITY;
            #pragma unroll
            for (int j = 1; j < 8; j++) mx = fmaxf(mx, l[i][j]);
            #pragma unroll
            for (int j = 0; j < 8; j++)
                if (c2base + j == ybr[i]) ly = l[i][j];
            mx = fmaxf(mx, __shfl_xor_sync(0xffffffffu, mx, 1));
            mx = fmaxf(mx, __shfl_xor_sync(0xffffffffu, mx, 2));
            ly = fmaxf(ly, __shfl_xor_sync(0xffffffffu, ly, 1));
            ly = fmaxf(ly, __shfl_xor_sync(0xffffffffu, ly, 2));
            if (csub == 0) {
                sm[OFF_EPMX + r * 8 + cw] = mx;
                sm[OFF_EPLY + r * 8 + cw] = ly;
            }
        }
        __syncthreads();   // S2

        // ---- epilogue phase 2: global max, partial exp-sums ----
        #pragma unroll
        for (int i = 0; i < 4; i++) {
            int r = rbase + i * 8;
            float4 m0 = *(const float4*)(sm + OFF_EPMX + r * 8);
            float4 m1 = *(const float4*)(sm + OFF_EPMX + r * 8 + 4);
            float gmx = fmaxf(fmaxf(fmaxf(m0.x, m0.y), fmaxf(m0.z, m0.w)),
                              fmaxf(fmaxf(m1.x, m1.y), fmaxf(m1.z, m1.w)));
            float s = 0.0f;
            #pragma unroll
            for (int j = 0; j < 8; j++) s += exp_match(l[i][j] - gmx);
            s += __shfl_xor_sync(0xffffffffu, s, 1);
            s += __shfl_xor_sync(0xffffffffu, s, 2);
            if (csub == 0) sm[OFF_EPS + r * 8 + cw] = s;
        }
        __syncthreads();   // S3

        // ---- score: one thread per row ----
        if (tid < RPB) {
            int r = tid;
            float4 m0 = *(const float4*)(sm + OFF_EPMX + r * 8);
            float4 m1 = *(const float4*)(sm + OFF_EPMX + r * 8 + 4);
            float gmx = fmaxf(fmaxf(fmaxf(m0.x, m0.y), fmaxf(m0.z, m0.w)),
                              fmaxf(fmaxf(m1.x, m1.y), fmaxf(m1.z, m1.w)));
            float4 y0 = *(const float4*)(sm + OFF_EPLY + r * 8);
            float4 y1 = *(const float4*)(sm + OFF_EPLY + r * 8 + 4);
            float ly = fmaxf(fmaxf(fmaxf(y0.x, y0.y), fmaxf(y0.z, y0.w)),
                             fmaxf(fmaxf(y1.x, y1.y), fmaxf(y1.z, y1.w)));
            float4 s0 = *(const float4*)(sm + OFF_EPS + r * 8);
            float4 s1 = *(const float4*)(sm + OFF_EPS + r * 8 + 4);
            float s = s0.x; s += s0.y; s += s0.z; s += s0.w;
            s += s1.x; s += s1.y; s += s1.z; s += s1.w;

            float e = exp_match(ly - gmx);
            float mass = e / s;
            float dens = mass * 256.0f;
            float d2 = dens + 1.401298464324817e-45f;
            float u = d2 - 1.0f;
            float sc;
            if (fabsf(u) < 1.220703125e-04f)       // 2^-13
                sc = fmaf(0.5f * u, u, -u);        // -RN(log1p(u))
            else
                sc = -logf(d2);
            acc += (double)sc;
        }
        buf ^= 1;
        // next iteration's S1 orders score-phase reads vs. new writes
    }

    // ---- deterministic block reduction ----
    if (tid < RPB) ((double*)(sm + OFF_DACC))[tid] = acc;
    __syncthreads();
    if (tid == 0) {
        double bs = 0.0;
        const double* sd = (const double*)(sm + OFF_DACC);
        #pragma unroll
        for (int r = 0; r < RPB; r++) bs += sd[r];
        g_partials[bid] = bs;
        __threadfence();
        unsigned int old = atomicInc(&g_done, gridDim.x - 1);
        if (old == gridDim.x - 1) {
            double tot = 0.0;
            for (int i = 0; i < (int)gridDim.x; i++)
                tot += ((volatile double*)g_partials)[i];
            out[0] = (float)tot;
        }
    }
}

extern "C" void kernel_launch(void* const* d_in, const int* in_sizes, int n_in,
                              void* d_out, int out_size)
{
    const float *X = 0, *Y = 0, *W1 = 0, *B1 = 0, *W2 = 0, *B2 = 0;
    long long nmax = 0;
    for (int i = 0; i < n_in; i++)
        if ((long long)in_sizes[i] > nmax) nmax = in_sizes[i];
    for (int i = 0; i < n_in; i++) {
        long long s = in_sizes[i];
        const float* p = (const float*)d_in[i];
        if (s == nmax)                X = p;
        else if (s == nmax / DIN)     Y = p;
        else if (s == DIN * HID)      W1 = p;
        else if (s == HID)            B1 = p;
        else if (s == HID * NBINS)    W2 = p;
        else if (s == NBINS)          B2 = p;
    }
    int nrows = (int)(nmax / DIN);
    int NT = nrows / RPB;

    int nsm = 148;
    cudaDeviceGetAttribute(&nsm, cudaDevAttrMultiProcessorCount, 0);
    if (nsm > MAXGRID) nsm = MAXGRID;
    int grid = (NT < nsm) ? NT : nsm;

    size_t smem = SMEM_FLOATS * sizeof(float);
    cudaFuncSetAttribute(mlp_loss_kernel,
                         cudaFuncAttributeMaxDynamicSharedMemorySize, (int)smem);
    mlp_loss_kernel<<<grid, TPB, smem>>>(X, Y, W1, B1, W2, B2, (float*)d_out, NT);
}